// round 6
// baseline (speedup 1.0000x reference)
#include <cuda_runtime.h>
#include <math.h>
#include <stdint.h>

// RandomizedOscillatorsNetwork: B=128, T=1024, I=64, H=512
// 16 clusters x 8 CTAs; cluster owns 8 batch rows; CTA owns 64 H-cols with its
// [576 x 64] weight slice (h2h || x2h) resident in SMEM. Per-step hy exchange via
// L2 (double-buffered __device__ array, [h][b] layout = straight 16KB memcpy).
// 512 threads: GEMM mapping 16 k-chunks (one per warp) x 32 col-groups (2 cols),
// packed fma.rn.f32x2 over batch pairs; scalar epilogue, hy register-resident.

#define DTc 0.042f
#define Bn 128
#define Tn 1024
#define In 64
#define Hn 512
#define NT 512
#define KTOT 576      // H + I
#define KC 16         // k-split chunks (one warp each)
#define KS 36         // k per chunk

#define W_BYTES   (KTOT*64*4)            // 147456
#define V2_OFF    (W_BYTES)
#define V2_BYTES  (KTOT*8*4)             // 18432  ([k][8 batch] floats)
#define RED_OFF   (V2_OFF + V2_BYTES)
#define RED_BYTES (KC*8*64*4)            // 32768  ([kc][b][col] floats)
#define SMEM_BYTES (RED_OFF + RED_BYTES) // 198656

typedef unsigned long long u64;

// double-buffered per-cluster hy exchange: [buf][cluster][h][b] floats (16KB per cluster)
__device__ float g_hy[2][16][Hn][8];

__device__ __forceinline__ u64 pack2(float lo, float hi) {
    u64 r; asm("mov.b64 %0, {%1, %2};" : "=l"(r) : "f"(lo), "f"(hi)); return r;
}
__device__ __forceinline__ void unpack2(u64 v, float& lo, float& hi) {
    asm("mov.b64 {%0, %1}, %2;" : "=f"(lo), "=f"(hi) : "l"(v));
}
__device__ __forceinline__ u64 ffma2(u64 a, u64 b, u64 c) {
    u64 d; asm("fma.rn.f32x2 %0, %1, %2, %3;" : "=l"(d) : "l"(a), "l"(b), "l"(c)); return d;
}

__global__ __launch_bounds__(NT, 1) __cluster_dims__(8, 1, 1)
void ron_kernel(const float* __restrict__ x, const float* __restrict__ x2h,
                const float* __restrict__ h2h, const float* __restrict__ bias,
                const float* __restrict__ gam, const float* __restrict__ eps,
                float* __restrict__ out, long long out_elems)
{
    extern __shared__ char smem[];
    float* W  = (float*)smem;                 // [KTOT][64] k-major, pitch 64 floats
    float* vf = (float*)(smem + V2_OFF);      // [KTOT][8]  (hy || x) per batch
    float* rf = (float*)(smem + RED_OFF);     // [KC][8][64] split-K partials

    const int tid  = threadIdx.x;
    const int cl   = blockIdx.x >> 3;    // cluster 0..15
    const int rank = blockIdx.x & 7;     // CTA rank
    const int c0   = rank * 64;          // H-column base
    const int b0   = cl * 8;             // batch base

    // prologue: resident weight slice W[k][j] = (k<H ? h2h[k][c0+j] : x2h[k-H][c0+j])
    for (int idx = tid; idx < KTOT*64; idx += NT) {
        int k = idx >> 6, j = idx & 63;
        W[idx] = (k < Hn) ? h2h[(size_t)k*Hn + c0 + j] : x2h[(size_t)(k - Hn)*Hn + c0 + j];
    }
    for (int idx = tid; idx < KTOT*8; idx += NT) vf[idx] = 0.f;

    // epilogue mapping: one scalar output per thread
    const int col = tid & 63, b = tid >> 6;   // b in 0..7
    const int hg  = c0 + col;
    const float bia = bias[hg], ga = gam[hg], ep = eps[hg];
    float hy = 0.f, hz = 0.f;                 // register-resident state

    // GEMM mapping: warp = one k-chunk, lane = col-group (2 cols)
    const int kc = tid >> 5, cg = tid & 31;
    const float* Wr0 = W  + kc*KS*64 + cg*2;
    const float* vr0 = vf + kc*KS*8;
    float*       rw  = rf + kc*512 + cg*2;

    // x prefetch: thread (b, i=col) owns x[b0+b][t][col]
    const float* xp = x + ((size_t)(b0 + b) * Tn) * In + col;
    float xr = xp[0];

    const size_t BTH = (size_t)Bn * Tn * Hn;
    const bool writeFinal = (out_elems >= (long long)(BTH + (size_t)Bn * Hn));

    __syncthreads();

    for (int t = 0; t < Tn; t++) {
        // (a) stage this step's x into vf (k >= 512 region)
        vf[(Hn + col)*8 + b] = xr;
        // (b) pull full cluster hy (written last step) from L2: flat 16KB copy
        if (t > 0) {
            const float4* src = (const float4*)&g_hy[(t - 1) & 1][cl][0][0]; // 1024 float4
            float4 v0 = src[tid];
            float4 v1 = src[tid + NT];
            ((float4*)vf)[tid]      = v0;
            ((float4*)vf)[tid + NT] = v1;
        }
        __syncthreads();

        // (c) GEMM: this warp's 36-k slice, 2 cols/thread, batch pairs packed f32x2
        u64 a00=0ull,a01=0ull,a10=0ull,a11=0ull,a20=0ull,a21=0ull,a30=0ull,a31=0ull;
        {
            const float* Wr = Wr0;
            const float* vr = vr0;
            #pragma unroll 6
            for (int kk = 0; kk < KS; kk++) {
                float2 wv = *(const float2*)(Wr + kk*64);              // conflict-free LDS.64
                ulonglong2 hA = *(const ulonglong2*)(vr + kk*8);       // broadcast b0..b3
                ulonglong2 hB = *(const ulonglong2*)(vr + kk*8 + 4);   // broadcast b4..b7
                u64 w0 = pack2(wv.x, wv.x);
                u64 w1 = pack2(wv.y, wv.y);
                a00 = ffma2(hA.x, w0, a00); a01 = ffma2(hA.x, w1, a01);
                a10 = ffma2(hA.y, w0, a10); a11 = ffma2(hA.y, w1, a11);
                a20 = ffma2(hB.x, w0, a20); a21 = ffma2(hB.x, w1, a21);
                a30 = ffma2(hB.y, w0, a30); a31 = ffma2(hB.y, w1, a31);
            }
        }
        // (d) stage split-K partials as [kc][b][col] (repack pairs -> per-batch float2)
        {
            float l0,h0,l1,h1;
            unpack2(a00,l0,h0); unpack2(a01,l1,h1);
            *(float2*)(rw + 0*64) = make_float2(l0,l1);
            *(float2*)(rw + 1*64) = make_float2(h0,h1);
            unpack2(a10,l0,h0); unpack2(a11,l1,h1);
            *(float2*)(rw + 2*64) = make_float2(l0,l1);
            *(float2*)(rw + 3*64) = make_float2(h0,h1);
            unpack2(a20,l0,h0); unpack2(a21,l1,h1);
            *(float2*)(rw + 4*64) = make_float2(l0,l1);
            *(float2*)(rw + 5*64) = make_float2(h0,h1);
            unpack2(a30,l0,h0); unpack2(a31,l1,h1);
            *(float2*)(rw + 6*64) = make_float2(l0,l1);
            *(float2*)(rw + 7*64) = make_float2(h0,h1);
        }
        __syncthreads();

        // (e) reduce + oscillator update + outputs (one scalar per thread)
        {
            float s = 0.f;
            const float* rr = rf + b*64 + col;   // lanes consecutive col -> conflict-free
            #pragma unroll
            for (int q = 0; q < KC; q++) s += rr[q*512];
            float th = tanhf(s + bia);
            hz += DTc * (th - ga*hy - ep*hz);
            hy += DTc * hz;
            out[((size_t)(b0 + b) * Tn + t) * Hn + hg] = hy;   // coalesced
            g_hy[t & 1][cl][hg][b] = hy;
            if (t == Tn - 1 && writeFinal)
                out[BTH + (size_t)(b0 + b) * Hn + hg] = hy;
            int tn = (t + 1 < Tn) ? (t + 1) : t;
            xr = xp[(size_t)tn * In];                           // prefetch next x
        }
        // (f) cluster barrier: release our g_hy STGs, acquire peers'
        asm volatile("barrier.cluster.arrive.aligned;" ::: "memory");
        asm volatile("barrier.cluster.wait.aligned;"   ::: "memory");
    }
}

extern "C" void kernel_launch(void* const* d_in, const int* in_sizes, int n_in,
                              void* d_out, int out_size) {
    const float* x    = (const float*)d_in[0];
    const float* x2h  = (const float*)d_in[1];
    const float* h2h  = (const float*)d_in[2];
    const float* bias = (const float*)d_in[3];
    const float* gam  = (const float*)d_in[4];
    const float* eps  = (const float*)d_in[5];
    float* out = (float*)d_out;
    (void)in_sizes; (void)n_in;

    cudaFuncSetAttribute(ron_kernel, cudaFuncAttributeMaxDynamicSharedMemorySize, SMEM_BYTES);
    ron_kernel<<<128, NT, SMEM_BYTES>>>(x, x2h, h2h, bias, gam, eps, out, (long long)out_size);
}